// round 6
// baseline (speedup 1.0000x reference)
#include <cuda_runtime.h>
#include <math.h>

#define ZNUM  64
#define CELLS 64
#define C1    64
#define C2    32
#define BMAX  64

// hidden activations h = silu(conv1(log1p(tof_map)))  [b][ic][cell]
__device__ float g_h[BMAX * C1 * CELLS];

// ---------- helpers ----------

__device__ __forceinline__ int read_dim(const void* p) {
    int   iv = ((const int*)p)[0];
    float fv = ((const float*)p)[0];
    bool int_ok = (iv >= 8 && iv <= 1000000);
    if (!int_ok && fv >= 8.f && fv <= 1.0e6f && floorf(fv) == fv) return (int)fv;
    return iv;
}

__device__ __forceinline__ int read_mask(const void* p, int idx, int layout) {
    if (layout == 0) return ((const int*)p)[idx] != 0;
    if (layout == 1) return ((const float*)p)[idx] != 0.0f;
    return ((const unsigned char*)p)[idx] != 0;
}

// packed fp32x2 fma: d = a*b + d  (full fp32 precision per lane)
__device__ __forceinline__ void ffma2(unsigned long long& d,
                                      unsigned long long a,
                                      unsigned long long b) {
    asm("fma.rn.f32x2 %0, %1, %2, %0;" : "+l"(d) : "l"(a), "l"(b));
}

// ---------- k1: prologue (pooling + log1p + 1x1 conv + SiLU) ----------

__global__ __launch_bounds__(256)
void kPro(const float* __restrict__ hist,     // [B,Z,2]
          const void*  __restrict__ maskp,    // [B,Z]
          const int*   __restrict__ fr,       // [B,Z,4]
          const void*  __restrict__ Hp, const void* __restrict__ Wp,
          const float* __restrict__ w1,       // [C1,2]
          const float* __restrict__ b1,       // [C1]
          int nwords)
{
    const int b   = blockIdx.x;
    const int tid = threadIdx.x;

    __shared__ int   s_sy[ZNUM], s_sx[ZNUM], s_ey[ZNUM], s_ex[ZNUM];
    __shared__ float s_mv[ZNUM], s_vv[ZNUM];
    __shared__ int   s_mk[ZNUM];
    __shared__ float s_x[CELLS][2];

    const int H = read_dim(Hp);
    const int W = read_dim(Wp);

    // mask layout detect (cooperative, bounded)
    int p_int = 1, p_float = 1;
    if (tid < 64) {
        const unsigned* mw = (const unsigned*)maskp;
        for (int i = 0; i < 4; ++i) {
            int idx = tid * 4 + i;
            if (idx < nwords) {
                unsigned v = mw[idx];
                if (v != 0u && v != 1u) p_int = 0;
                if (v != 0u && v != 0x3F800000u) p_float = 0;
            }
        }
    }
    if (tid < ZNUM) {
        const int z = tid;
        const int* bx = fr + ((long)b * ZNUM + z) * 4;
        s_sy[z] = max(bx[0], 0);
        s_sx[z] = max(bx[1], 0);
        s_ey[z] = min(bx[2], H);
        s_ex[z] = min(bx[3], W);
        s_mv[z] = hist[((long)b * ZNUM + z) * 2 + 0];
        s_vv[z] = hist[((long)b * ZNUM + z) * 2 + 1];
    }
    int all_int   = __syncthreads_and(p_int);
    int all_float = __syncthreads_and(p_float);
    const int mlayout = all_int ? 0 : (all_float ? 1 : 2);
    if (tid < ZNUM)
        s_mk[tid] = read_mask(maskp, b * ZNUM + tid, mlayout);
    __syncthreads();

    const int bh = H / 8, bw = W / 8;
    const float inv_area = 1.0f / (float)(bh * bw);

    if (tid < CELLS) {
        const int r = tid >> 3, c = tid & 7;
        const int cy0 = r * bh, cy1 = cy0 + bh;
        const int cx0 = c * bw, cx1 = cx0 + bw;
        float sm = 0.f, sv = 0.f;
        bool fb = false;
        for (int z = ZNUM - 1; z >= 0; --z) {          // last-write-wins
            if (!s_mk[z]) continue;
            int iy0 = max(s_sy[z], cy0), iy1 = min(s_ey[z], cy1);
            int ix0 = max(s_sx[z], cx0), ix1 = min(s_ex[z], cx1);
            if (iy0 >= iy1 || ix0 >= ix1) continue;
            if (iy0 == cy0 && iy1 == cy1 && ix0 == cx0 && ix1 == cx1) {
                sm = s_mv[z] * (float)(bh * bw);
                sv = s_vv[z] * (float)(bh * bw);
            } else {
                fb = true;   // partial cover -> exact per-pixel fallback
            }
            break;
        }
        if (fb) {
            sm = 0.f; sv = 0.f;
            for (int y = cy0; y < cy1; ++y)
                for (int x = cx0; x < cx1; ++x)
                    for (int z = ZNUM - 1; z >= 0; --z) {
                        if (!s_mk[z]) continue;
                        if (y >= s_sy[z] && y < s_ey[z] &&
                            x >= s_sx[z] && x < s_ex[z]) {
                            sm += s_mv[z]; sv += s_vv[z];
                            break;
                        }
                    }
        }
        float tm = sm * inv_area, tv = sv * inv_area;
        s_x[tid][0] = log1pf(fmaxf(tm, 0.f));
        s_x[tid][1] = log1pf(fmaxf(tv, 0.f));
    }
    __syncthreads();

    for (int i = tid; i < C1 * CELLS; i += 256) {
        const int ch = i >> 6, cell = i & 63;
        float v = fmaf(w1[ch * 2 + 0], s_x[cell][0],
                  fmaf(w1[ch * 2 + 1], s_x[cell][1], b1[ch]));
        g_h[(long)b * C1 * CELLS + i] = v * (1.0f / (1.0f + __expf(-v)));
    }
}

// ---------- k2: 3x3 conv as 9-tap GEMM + shift-add ----------
// grid (8, B): block = (4 oc, b). 288 threads = 9 warps; warp = tap t.
// lane owns cells {2l, 2l+1} x 4 oc -> 4 f32x2 accumulators.

__global__ __launch_bounds__(288)
void kConv(const float* __restrict__ w2,   // [C2,C1,3,3]
           const float* __restrict__ b2,   // [C2]
           float* __restrict__ out)        // [B,C2,64]
{
    const int ocg  = blockIdx.x;           // 0..7 -> oc base ocg*4
    const int b    = blockIdx.y;
    const int tid  = threadIdx.x;
    const int warp = tid >> 5;             // tap 0..8
    const int lane = tid & 31;

    __shared__ __align__(16) float hs[C1 * 64];        // 16 KB  [ic][cell]
    __shared__ __align__(16) float wsd[9 * 64 * 8];    // 18 KB  [t][ic][ol][2] dup
    __shared__ __align__(16) float U[9 * 4 * 64];      //  9 KB  [t][ol][cell]

    // stage H (16 KB, float4)
    {
        const float* hb = g_h + (long)b * C1 * CELLS;
        for (int i = tid * 4; i < C1 * 64; i += 288 * 4)
            *(float4*)(hs + i) = *(const float4*)(hb + i);
    }
    // stage duplicated weights: wsd[t*256 + ic*4 + ol] pair
    {
        const int oc0 = ocg * 4;
        for (int i = tid; i < 9 * 64 * 4; i += 288) {
            int ol = i & 3, ic = (i >> 2) & 63, t = i >> 8;
            float v = w2[(oc0 + ol) * 576 + ic * 9 + t];
            wsd[i * 2 + 0] = v;
            wsd[i * 2 + 1] = v;
        }
    }
    __syncthreads();

    // GEMM: U_t[ol][cells] += W[ol][ic][t] * H[ic][cells]
    unsigned long long a0 = 0, a1 = 0, a2 = 0, a3 = 0;
    {
        const float* wt = wsd + warp * 512;      // [ic][ol*2]
        const float* hp = hs + 2 * lane;
#pragma unroll
        for (int ic = 0; ic < 64; ++ic) {
            unsigned long long h = *(const unsigned long long*)(hp + ic * 64);
            ulonglong2 w01 = *(const ulonglong2*)(wt + ic * 8);
            ulonglong2 w23 = *(const ulonglong2*)(wt + ic * 8 + 4);
            ffma2(a0, w01.x, h);
            ffma2(a1, w01.y, h);
            ffma2(a2, w23.x, h);
            ffma2(a3, w23.y, h);
        }
    }

    // write U
    {
        float* up = U + warp * 256 + 2 * lane;
        *(unsigned long long*)(up +   0) = a0;
        *(unsigned long long*)(up +  64) = a1;
        *(unsigned long long*)(up + 128) = a2;
        *(unsigned long long*)(up + 192) = a3;
    }
    __syncthreads();

    // epilogue: combine 9 shifted taps; thread < 256 owns one output element
    if (tid < 256) {
        const int ol = tid >> 6, cell = tid & 63;
        const int y = cell >> 3, x = cell & 7;
        float s = b2[ocg * 4 + ol];
#pragma unroll
        for (int t = 0; t < 9; ++t) {
            const int yy = y + t / 3 - 1;
            const int xx = x + t % 3 - 1;
            if (yy >= 0 && yy < 8 && xx >= 0 && xx < 8)
                s += U[t * 256 + ol * 64 + yy * 8 + xx];
        }
        out[((long)b * C2 + ocg * 4 + ol) * 64 + cell] = s;
    }
}

// ---------- launch ----------

extern "C" void kernel_launch(void* const* d_in, const int* in_sizes, int n_in,
                              void* d_out, int out_size)
{
    // input order: hist_BZ2, mask_BZ, fr_BZ4, H, W, w1, b1, w2, b2
    const float* hist  = (const float*)d_in[0];
    const void*  maskp = d_in[1];
    const int*   fr    = (const int*)d_in[2];
    const void*  Hp    = d_in[3];
    const void*  Wp    = d_in[4];
    const float* w1    = (const float*)d_in[5];
    const float* b1    = (const float*)d_in[6];
    const float* w2    = (const float*)d_in[7];
    const float* b2    = (const float*)d_in[8];
    float* out = (float*)d_out;

    int B = in_sizes[1] / ZNUM;
    if (B < 1) B = 1;
    if (B > BMAX) B = BMAX;

    int nwords = in_sizes[1] / 4;
    if (nwords > 256) nwords = 256;
    if (nwords < 1) nwords = 1;

    kPro<<<B, 256>>>(hist, maskp, fr, Hp, Wp, w1, b1, nwords);
    kConv<<<dim3(8, B), 288>>>(w2, b2, out);
}

// round 10
// speedup vs baseline: 1.0757x; 1.0757x over previous
#include <cuda_runtime.h>
#include <math.h>

#define ZNUM  64
#define CELLS 64
#define C1    64
#define C2    32
#define BMAX  64

typedef unsigned long long ull;

// ---------- helpers ----------

__device__ __forceinline__ int read_dim(const void* p) {
    int   iv = ((const int*)p)[0];
    float fv = ((const float*)p)[0];
    bool int_ok = (iv >= 8 && iv <= 1000000);
    if (!int_ok && fv >= 8.f && fv <= 1.0e6f && floorf(fv) == fv) return (int)fv;
    return iv;
}

__device__ __forceinline__ int read_mask(const void* p, int idx, int layout) {
    if (layout == 0) return ((const int*)p)[idx] != 0;
    if (layout == 1) return ((const float*)p)[idx] != 0.0f;
    return ((const unsigned char*)p)[idx] != 0;
}

__device__ __forceinline__ void ffma2(ull& d, ull a, ull b) {
    asm("fma.rn.f32x2 %0, %1, %2, %0;" : "+l"(d) : "l"(a), "l"(b));
}
__device__ __forceinline__ ull pack2(float v) {
    ull r;
    asm("mov.b64 %0, {%1, %1};" : "=l"(r) : "f"(v));
    return r;
}

// ---------- fused kernel ----------
// grid (4, B): block = 8 oc.  128 threads = 4 warps; warp = oc pair (2w, 2w+1).
// lane owns cells {lane, lane+32}; f32x2 packs the oc pair.

__global__ __launch_bounds__(128)
void kFused(const float* __restrict__ hist,     // [B,Z,2]
            const void*  __restrict__ maskp,    // [B,Z]
            const int*   __restrict__ fr,       // [B,Z,4]
            const void*  __restrict__ Hp, const void* __restrict__ Wp,
            const float* __restrict__ w1,       // [C1,2]
            const float* __restrict__ b1,       // [C1]
            const float* __restrict__ w2,       // [C2,C1,3,3]
            const float* __restrict__ b2,       // [C2]
            float* __restrict__ out,            // [B,C2,64]
            int nwords)
{
    const int ocg = blockIdx.x;       // oc base = ocg*8
    const int b   = blockIdx.y;
    const int tid = threadIdx.x;

    __shared__ int   s_sy[ZNUM], s_sx[ZNUM], s_ey[ZNUM], s_ex[ZNUM];
    __shared__ float s_mv[ZNUM], s_vv[ZNUM];
    __shared__ int   s_mk[ZNUM];
    __shared__ float s_x[CELLS][2];
    __shared__ __align__(16) float hs[C1 * 64];       // 16 KB [ic][cell]
    __shared__ __align__(16) float wpair[4 * 64 * 20]; // 20 KB [w][ic][10 ull];
                                                       // aliased as U after mainloop

    const int H = read_dim(Hp);
    const int W = read_dim(Wp);

    // ---- mask layout detect (cooperative, bounded) ----
    int p_int = 1, p_float = 1;
    if (tid < 64) {
        const unsigned* mw = (const unsigned*)maskp;
        for (int i = 0; i < 4; ++i) {
            int idx = tid * 4 + i;
            if (idx < nwords) {
                unsigned v = mw[idx];
                if (v != 0u && v != 1u) p_int = 0;
                if (v != 0u && v != 0x3F800000u) p_float = 0;
            }
        }
    }
    if (tid < ZNUM) {
        const int z = tid;
        const int* bx = fr + ((long)b * ZNUM + z) * 4;
        s_sy[z] = max(bx[0], 0);
        s_sx[z] = max(bx[1], 0);
        s_ey[z] = min(bx[2], H);
        s_ex[z] = min(bx[3], W);
        s_mv[z] = hist[((long)b * ZNUM + z) * 2 + 0];
        s_vv[z] = hist[((long)b * ZNUM + z) * 2 + 1];
    }
    int all_int   = __syncthreads_and(p_int);
    int all_float = __syncthreads_and(p_float);
    const int mlayout = all_int ? 0 : (all_float ? 1 : 2);
    if (tid < ZNUM)
        s_mk[tid] = read_mask(maskp, b * ZNUM + tid, mlayout);
    __syncthreads();

    // ---- pooling (lazy exact scatter+area-pool) + log1p ----
    const int bh = H / 8, bw = W / 8;
    const float inv_area = 1.0f / (float)(bh * bw);

    if (tid < CELLS) {
        const int r = tid >> 3, c = tid & 7;
        const int cy0 = r * bh, cy1 = cy0 + bh;
        const int cx0 = c * bw, cx1 = cx0 + bw;
        float sm = 0.f, sv = 0.f;
        bool fb = false;
        for (int z = ZNUM - 1; z >= 0; --z) {          // last-write-wins
            if (!s_mk[z]) continue;
            int iy0 = max(s_sy[z], cy0), iy1 = min(s_ey[z], cy1);
            int ix0 = max(s_sx[z], cx0), ix1 = min(s_ex[z], cx1);
            if (iy0 >= iy1 || ix0 >= ix1) continue;
            if (iy0 == cy0 && iy1 == cy1 && ix0 == cx0 && ix1 == cx1) {
                sm = s_mv[z] * (float)(bh * bw);
                sv = s_vv[z] * (float)(bh * bw);
            } else {
                fb = true;  // partial cover -> exact per-pixel fallback
            }
            break;
        }
        if (fb) {
            sm = 0.f; sv = 0.f;
            for (int y = cy0; y < cy1; ++y)
                for (int x = cx0; x < cx1; ++x)
                    for (int z = ZNUM - 1; z >= 0; --z) {
                        if (!s_mk[z]) continue;
                        if (y >= s_sy[z] && y < s_ey[z] &&
                            x >= s_sx[z] && x < s_ex[z]) {
                            sm += s_mv[z]; sv += s_vv[z];
                            break;
                        }
                    }
        }
        float tm = sm * inv_area, tv = sv * inv_area;
        s_x[tid][0] = log1pf(fmaxf(tm, 0.f));
        s_x[tid][1] = log1pf(fmaxf(tv, 0.f));
    }

    // ---- stage weight pairs (independent of s_x): wpair[w][ic][2t+s] ----
    {
        const int oc0 = ocg * 8;
        for (int i = tid; i < 4 * 64 * 9; i += 128) {
            int t = i % 9, ic = (i / 9) & 63, w = i / 576;
            float* dst = wpair + (w * 64 + ic) * 20 + 2 * t;
            dst[0] = w2[(oc0 + 2 * w + 0) * 576 + ic * 9 + t];
            dst[1] = w2[(oc0 + 2 * w + 1) * 576 + ic * 9 + t];
        }
    }
    __syncthreads();

    // ---- 1x1 conv (2 -> C1) + SiLU into hs ----
    for (int i = tid; i < C1 * CELLS; i += 128) {
        const int ch = i >> 6, cell = i & 63;
        float v = fmaf(w1[ch * 2 + 0], s_x[cell][0],
                  fmaf(w1[ch * 2 + 1], s_x[cell][1], b1[ch]));
        hs[i] = v * (1.0f / (1.0f + __expf(-v)));
    }
    __syncthreads();

    // ---- mainloop: 9-tap GEMM, oc pair packed in f32x2 ----
    const int w    = tid >> 5;
    const int lane = tid & 31;

    ull a0[9], a1[9];
#pragma unroll
    for (int t = 0; t < 9; ++t) { a0[t] = 0; a1[t] = 0; }

    {
        const float* wp = wpair + w * 1280;
#pragma unroll 16
        for (int ic = 0; ic < 64; ++ic) {
            const ull H0 = pack2(hs[ic * 64 + lane]);
            const ull H1 = pack2(hs[ic * 64 + 32 + lane]);
            const float* q = wp + ic * 20;
            ulonglong2 p01 = *(const ulonglong2*)(q);
            ulonglong2 p23 = *(const ulonglong2*)(q + 4);
            ulonglong2 p45 = *(const ulonglong2*)(q + 8);
            ulonglong2 p67 = *(const ulonglong2*)(q + 12);
            ull        p8  = *(const ull*)(q + 16);
            ffma2(a0[0], p01.x, H0);  ffma2(a1[0], p01.x, H1);
            ffma2(a0[1], p01.y, H0);  ffma2(a1[1], p01.y, H1);
            ffma2(a0[2], p23.x, H0);  ffma2(a1[2], p23.x, H1);
            ffma2(a0[3], p23.y, H0);  ffma2(a1[3], p23.y, H1);
            ffma2(a0[4], p45.x, H0);  ffma2(a1[4], p45.x, H1);
            ffma2(a0[5], p45.y, H0);  ffma2(a1[5], p45.y, H1);
            ffma2(a0[6], p67.x, H0);  ffma2(a1[6], p67.x, H1);
            ffma2(a0[7], p67.y, H0);  ffma2(a1[7], p67.y, H1);
            ffma2(a0[8], p8,    H0);  ffma2(a1[8], p8,    H1);
        }
    }

    __syncthreads();   // all warps done reading wpair -> safe to alias as U

    // U layout: float U[t][w][cell][2]  (aliased on wpair, 18432 B)
    {
        float* Ub = wpair;
#pragma unroll
        for (int t = 0; t < 9; ++t) {
            *(ull*)(Ub + ((t * 4 + w) * 64 + lane) * 2)        = a0[t];
            *(ull*)(Ub + ((t * 4 + w) * 64 + 32 + lane) * 2)   = a1[t];
        }
    }
    __syncthreads();

    // ---- epilogue: shift-add 9 taps; 4 outputs per thread ----
    {
        const float* Ub = wpair;
        const int oc0 = ocg * 8;
#pragma unroll
        for (int r = 0; r < 4; ++r) {
            const int j    = tid + r * 128;      // 0..511
            const int oc_l = j >> 6;             // 0..7
            const int cell = j & 63;
            const int wq   = oc_l >> 1;
            const int s    = oc_l & 1;
            const int y = cell >> 3, x = cell & 7;
            float sum = b2[oc0 + oc_l];
#pragma unroll
            for (int t = 0; t < 9; ++t) {
                const int yy = y + t / 3 - 1;
                const int xx = x + t % 3 - 1;
                if (yy >= 0 && yy < 8 && xx >= 0 && xx < 8)
                    sum += Ub[((t * 4 + wq) * 64 + yy * 8 + xx) * 2 + s];
            }
            out[((long)b * C2 + oc0 + oc_l) * 64 + cell] = sum;
        }
    }
}

// ---------- launch ----------

extern "C" void kernel_launch(void* const* d_in, const int* in_sizes, int n_in,
                              void* d_out, int out_size)
{
    // input order: hist_BZ2, mask_BZ, fr_BZ4, H, W, w1, b1, w2, b2
    const float* hist  = (const float*)d_in[0];
    const void*  maskp = d_in[1];
    const int*   fr    = (const int*)d_in[2];
    const void*  Hp    = d_in[3];
    const void*  Wp    = d_in[4];
    const float* w1    = (const float*)d_in[5];
    const float* b1    = (const float*)d_in[6];
    const float* w2    = (const float*)d_in[7];
    const float* b2    = (const float*)d_in[8];
    float* out = (float*)d_out;

    int B = in_sizes[1] / ZNUM;
    if (B < 1) B = 1;
    if (B > BMAX) B = BMAX;

    int nwords = in_sizes[1] / 4;
    if (nwords > 256) nwords = 256;
    if (nwords < 1) nwords = 1;

    kFused<<<dim3(4, B), 128>>>(hist, maskp, fr, Hp, Wp,
                                w1, b1, w2, b2, out, nwords);
}